// round 12
// baseline (speedup 1.0000x reference)
#include <cuda_runtime.h>
#include <cuda_bf16.h>
#include <cstdint>
#include <cstddef>

// ---------------- problem constants ----------------
#define N_NODES 50000
#define N_EDGES 800000
#define T_STEPS 6

__device__ float g_scratch[124000000];
// preconverted weights: 14 matrices, 212992 elements, hi + lo
__device__ __nv_bfloat16 g_wbf[425984];

// ============================================================================
// Weight pre-conversion: fp32 W[K,F] -> bf16 hi/lo, transposed to [F][K]
// ============================================================================
struct WCvt { const float* w; int K; int F; int off; };
struct WCvtTab { WCvt m[14]; };

__global__ void convw_k(WCvtTab tab, __nv_bfloat16* __restrict__ hi,
                        __nv_bfloat16* __restrict__ lo) {
    WCvt d = tab.m[blockIdx.y];
    int idx = blockIdx.x * 256 + threadIdx.x;
    if (idx >= d.K * d.F) return;
    int f = idx / d.K, k = idx % d.K;
    float v = d.w[(size_t)k * d.F + f];
    __nv_bfloat16 h = __float2bfloat16(v);
    hi[d.off + idx] = h;
    lo[d.off + idx] = __float2bfloat16(v - __bfloat162float(h));
}

// ============================================================================
// bf16-split tensor-core GEMM via mma.sync + ldmatrix (round-9 configuration)
// ============================================================================
__device__ __forceinline__ void mma16816(float* c, uint32_t a0, uint32_t a1,
                                         uint32_t a2, uint32_t a3,
                                         uint32_t b0, uint32_t b1) {
    asm volatile(
        "mma.sync.aligned.m16n8k16.row.col.f32.bf16.bf16.f32 "
        "{%0,%1,%2,%3}, {%4,%5,%6,%7}, {%8,%9}, {%0,%1,%2,%3};"
        : "+f"(c[0]), "+f"(c[1]), "+f"(c[2]), "+f"(c[3])
        : "r"(a0), "r"(a1), "r"(a2), "r"(a3), "r"(b0), "r"(b1));
}

__device__ __forceinline__ void ldsm_x4(uint32_t& r0, uint32_t& r1, uint32_t& r2,
                                        uint32_t& r3, uint32_t addr) {
    asm volatile("ldmatrix.sync.aligned.m8n8.x4.shared.b16 {%0,%1,%2,%3}, [%4];"
                 : "=r"(r0), "=r"(r1), "=r"(r2), "=r"(r3) : "r"(addr));
}

__device__ __forceinline__ uint32_t smem_u32(const void* p) {
    uint32_t a;
    asm("{ .reg .u64 t; cvta.to.shared.u64 t, %1; cvt.u32.u64 %0, t; }" : "=r"(a) : "l"(p));
    return a;
}

#define CP_ASYNC16(smem_addr, gptr) \
    asm volatile("cp.async.cg.shared.global [%0], [%1], 16;" \
                 :: "r"(smem_addr), "l"(gptr))
#define CP_ASYNC_COMMIT() asm volatile("cp.async.commit_group;" ::: "memory")
#define CP_ASYNC_WAIT0()  asm volatile("cp.async.wait_group 0;" ::: "memory")

template <int BM, int K>
__device__ __forceinline__ void load_a_tile(const float* __restrict__ A, int bm, int M,
                                            uint16_t* Ah, uint16_t* Al, int tid) {
    constexpr int SK = K + 8;
    for (int i = tid * 4; i < BM * K; i += 256 * 4) {
        int row = i / K;
        int k = i % K;
        int g = bm + row;
        float4 v = make_float4(0.f, 0.f, 0.f, 0.f);
        if (g < M) v = *reinterpret_cast<const float4*>(A + (size_t)g * K + k);
        float2 p0 = make_float2(v.x, v.y);
        float2 p1 = make_float2(v.z, v.w);
        __nv_bfloat162 h0 = __float22bfloat162_rn(p0);
        __nv_bfloat162 h1 = __float22bfloat162_rn(p1);
        float2 b0 = __bfloat1622float2(h0);
        float2 b1 = __bfloat1622float2(h1);
        __nv_bfloat162 l0 = __float22bfloat162_rn(make_float2(p0.x - b0.x, p0.y - b0.y));
        __nv_bfloat162 l1 = __float22bfloat162_rn(make_float2(p1.x - b1.x, p1.y - b1.y));
        uint2 hv, lv;
        hv.x = *reinterpret_cast<uint32_t*>(&h0);
        hv.y = *reinterpret_cast<uint32_t*>(&h1);
        lv.x = *reinterpret_cast<uint32_t*>(&l0);
        lv.y = *reinterpret_cast<uint32_t*>(&l1);
        *reinterpret_cast<uint2*>(Ah + row * SK + k) = hv;
        *reinterpret_cast<uint2*>(Al + row * SK + k) = lv;
    }
}

template <int F, int K>
__device__ __forceinline__ void issue_w_copy(const __nv_bfloat16* __restrict__ Whi,
                                             const __nv_bfloat16* __restrict__ Wlo,
                                             uint16_t* Wh, uint16_t* Wl, int tid) {
    constexpr int SK = K + 8;
    for (int i = tid; i < F * (K / 8); i += 256) {
        int row = i / (K / 8);
        int kc = (i % (K / 8)) * 8;
        CP_ASYNC16(smem_u32(Wh + row * SK + kc), Whi + (size_t)row * K + kc);
        CP_ASYNC16(smem_u32(Wl + row * SK + kc), Wlo + (size_t)row * K + kc);
    }
    CP_ASYNC_COMMIT();
}

template <int MFR, int NPAIR, int KSTEPS>
__device__ __forceinline__ void mainloop(const uint16_t* Ah, const uint16_t* Al,
                                         const uint16_t* Wh, const uint16_t* Wl,
                                         const int* a_off, const int* b_off,
                                         float (*acc)[4]) {
    const uint16_t* Asel[3] = {Ah, Ah, Al};
    const uint16_t* Bsel[3] = {Wh, Wl, Wh};
#pragma unroll
    for (int p = 0; p < 3; p++) {
        const uint32_t abase = smem_u32(Asel[p]);
        const uint32_t bbase = smem_u32(Bsel[p]);
#pragma unroll
        for (int ks = 0; ks < KSTEPS; ks++) {
            uint32_t af[MFR][4];
#pragma unroll
            for (int mi = 0; mi < MFR; mi++)
                ldsm_x4(af[mi][0], af[mi][1], af[mi][2], af[mi][3],
                        abase + a_off[mi] + ks * 32);
            uint32_t bf[NPAIR][4];
#pragma unroll
            for (int pr = 0; pr < NPAIR; pr++)
                ldsm_x4(bf[pr][0], bf[pr][1], bf[pr][2], bf[pr][3],
                        bbase + b_off[pr] + ks * 32);
#pragma unroll
            for (int pr = 0; pr < NPAIR; pr++)
#pragma unroll
                for (int half = 0; half < 2; half++) {
                    uint32_t b0 = bf[pr][half * 2 + 0];
                    uint32_t b1 = bf[pr][half * 2 + 1];
#pragma unroll
                    for (int mi = 0; mi < MFR; mi++)
                        mma16816(acc[mi * NPAIR * 2 + pr * 2 + half],
                                 af[mi][0], af[mi][1], af[mi][2], af[mi][3], b0, b1);
                }
        }
    }
}

template <int F, int K>
__global__ void __launch_bounds__(256, 2)
tcgemm_k(const float* __restrict__ A,
         const __nv_bfloat16* __restrict__ Whi, const __nv_bfloat16* __restrict__ Wlo,
         float* __restrict__ C, int M,
         const float* __restrict__ Cadd, const float* __restrict__ bias, int act) {
    constexpr int BM = 64;
    constexpr int SK = K + 8;
    constexpr int WARPS_N = F / 32;
    constexpr int WARPS_M = 8 / WARPS_N;
    constexpr int WTM = BM / WARPS_M;
    constexpr int MFR = WTM / 16;
    constexpr int NFR = 4;
    constexpr int NPAIR = NFR / 2;
    constexpr int KSTEPS = K / 16;

    extern __shared__ char sm[];
    uint16_t* Ah = reinterpret_cast<uint16_t*>(sm);
    uint16_t* Al = Ah + BM * SK;
    uint16_t* Wh = Al + BM * SK;
    uint16_t* Wl = Wh + F * SK;

    const int tid = threadIdx.x;
    const int warp = tid >> 5;
    const int lane = tid & 31;
    const int bm = blockIdx.x * BM;
    const int wm = warp % WARPS_M;
    const int wn = warp / WARPS_M;
    const int rb = wm * WTM;
    const int cb = wn * 32;

    issue_w_copy<F, K>(Whi, Wlo, Wh, Wl, tid);
    load_a_tile<BM, K>(A, bm, M, Ah, Al, tid);
    CP_ASYNC_WAIT0();
    __syncthreads();

    float acc[MFR * NFR][4];
#pragma unroll
    for (int q = 0; q < MFR * NFR; q++) {
        acc[q][0] = 0.f; acc[q][1] = 0.f; acc[q][2] = 0.f; acc[q][3] = 0.f;
    }

    int a_off[MFR], b_off[NPAIR];
#pragma unroll
    for (int mi = 0; mi < MFR; mi++)
        a_off[mi] = ((rb + mi * 16 + (lane & 7) + ((lane >> 3) & 1) * 8) * SK +
                     ((lane >> 4) & 1) * 8) * 2;
#pragma unroll
    for (int pr = 0; pr < NPAIR; pr++)
        b_off[pr] = ((cb + pr * 16 + ((lane >> 4) & 1) * 8 + (lane & 7)) * SK +
                     ((lane >> 3) & 1) * 8) * 2;

    mainloop<MFR, NPAIR, KSTEPS>(Ah, Al, Wh, Wl, a_off, b_off, acc);

    const int gq = lane >> 2;
    const int tq = lane & 3;
#pragma unroll
    for (int mi = 0; mi < MFR; mi++) {
#pragma unroll
        for (int half = 0; half < 2; half++) {
            int gr = bm + rb + mi * 16 + gq + half * 8;
            if (gr >= M) continue;
#pragma unroll
            for (int ni = 0; ni < NFR; ni++) {
                int gc = cb + ni * 8 + tq * 2;
                float v0 = acc[mi * NFR + ni][half * 2 + 0];
                float v1 = acc[mi * NFR + ni][half * 2 + 1];
                if (Cadd) {
                    float2 a = *reinterpret_cast<const float2*>(Cadd + (size_t)gr * F + gc);
                    v0 += a.x; v1 += a.y;
                }
                if (bias) {
                    float2 b = *reinterpret_cast<const float2*>(bias + gc);
                    v0 += b.x; v1 += b.y;
                }
                if (act) { v0 = fmaxf(v0, 0.f); v1 = fmaxf(v1, 0.f); }
                float2 o; o.x = v0; o.y = v1;
                *reinterpret_cast<float2*>(C + (size_t)gr * F + gc) = o;
            }
        }
    }
}

// fused dual-(A,W): C = A1@W1 + A2@W2 + Cadd  (F=128, K=128), 2-phase SMEM reuse
__global__ void __launch_bounds__(256, 2)
tcgemm2_k(const float* __restrict__ A1,
          const __nv_bfloat16* __restrict__ W1h, const __nv_bfloat16* __restrict__ W1l,
          const float* __restrict__ A2,
          const __nv_bfloat16* __restrict__ W2h, const __nv_bfloat16* __restrict__ W2l,
          float* __restrict__ C, int M, const float* __restrict__ Cadd) {
    constexpr int F = 128, K = 128, BM = 64;
    constexpr int SK = K + 8;
    constexpr int WARPS_M = 2;
    constexpr int KSTEPS = 8;

    extern __shared__ char sm[];
    uint16_t* Ah = reinterpret_cast<uint16_t*>(sm);
    uint16_t* Al = Ah + BM * SK;
    uint16_t* Wh = Al + BM * SK;
    uint16_t* Wl = Wh + F * SK;

    const int tid = threadIdx.x;
    const int warp = tid >> 5;
    const int lane = tid & 31;
    const int bm = blockIdx.x * BM;
    const int wm = warp % WARPS_M;
    const int wn = warp / WARPS_M;
    const int rb = wm * 32;
    const int cb = wn * 32;

    float acc[8][4];
#pragma unroll
    for (int q = 0; q < 8; q++) {
        acc[q][0] = 0.f; acc[q][1] = 0.f; acc[q][2] = 0.f; acc[q][3] = 0.f;
    }

    int a_off[2], b_off[2];
#pragma unroll
    for (int mi = 0; mi < 2; mi++)
        a_off[mi] = ((rb + mi * 16 + (lane & 7) + ((lane >> 3) & 1) * 8) * SK +
                     ((lane >> 4) & 1) * 8) * 2;
#pragma unroll
    for (int pr = 0; pr < 2; pr++)
        b_off[pr] = ((cb + pr * 16 + ((lane >> 4) & 1) * 8 + (lane & 7)) * SK +
                     ((lane >> 3) & 1) * 8) * 2;

#pragma unroll
    for (int seg = 0; seg < 2; seg++) {
        if (seg) __syncthreads();
        const float* A = seg ? A2 : A1;
        const __nv_bfloat16* whi = seg ? W2h : W1h;
        const __nv_bfloat16* wlo = seg ? W2l : W1l;
        issue_w_copy<F, K>(whi, wlo, Wh, Wl, tid);
        load_a_tile<BM, K>(A, bm, M, Ah, Al, tid);
        CP_ASYNC_WAIT0();
        __syncthreads();
        mainloop<2, 2, KSTEPS>(Ah, Al, Wh, Wl, a_off, b_off, acc);
    }

    const int gq = lane >> 2;
    const int tq = lane & 3;
#pragma unroll
    for (int mi = 0; mi < 2; mi++) {
#pragma unroll
        for (int half = 0; half < 2; half++) {
            int gr = bm + rb + mi * 16 + gq + half * 8;
            if (gr >= M) continue;
#pragma unroll
            for (int ni = 0; ni < 4; ni++) {
                int gc = cb + ni * 8 + tq * 2;
                float v0 = acc[mi * 4 + ni][half * 2 + 0];
                float v1 = acc[mi * 4 + ni][half * 2 + 1];
                float2 a = *reinterpret_cast<const float2*>(Cadd + (size_t)gr * F + gc);
                v0 += a.x; v1 += a.y;
                float2 o; o.x = v0; o.y = v1;
                *reinterpret_cast<float2*>(C + (size_t)gr * F + gc) = o;
            }
        }
    }
}

// ---------------- batched CSR build (all 6 timesteps at once) ----------------
__global__ void count6_k(const int* __restrict__ ei, int* __restrict__ cntA, int e) {
    int t = blockIdx.y;
    int i = blockIdx.x * blockDim.x + threadIdx.x;
    if (i < e) {
        const int* dst = ei + (size_t)t * 2 * e + e;
        atomicAdd(&cntA[t * N_NODES + dst[i]], 1);
    }
}

__global__ void dis6_k(const int* __restrict__ cntA, float* __restrict__ disA, int n) {
    int t = blockIdx.y;
    int i = blockIdx.x * blockDim.x + threadIdx.x;
    if (i < n) disA[t * n + i] = rsqrtf(1.0f + (float)cntA[t * n + i]);
}

__global__ void scan1_k(const int* __restrict__ cntA, int* __restrict__ offA,
                        int* __restrict__ bsumA, int n) {
    int t = blockIdx.y;
    const int* cnt = cntA + t * n;
    int* off = offA + t * n;
    int* bsum = bsumA + t * 64;
    __shared__ int sh[1024];
    int gid = blockIdx.x * 1024 + threadIdx.x;
    int v = (gid < n) ? cnt[gid] : 0;
    sh[threadIdx.x] = v;
    __syncthreads();
    for (int d = 1; d < 1024; d <<= 1) {
        int u = (threadIdx.x >= d) ? sh[threadIdx.x - d] : 0;
        __syncthreads();
        sh[threadIdx.x] += u;
        __syncthreads();
    }
    if (gid < n) off[gid] = sh[threadIdx.x] - v;
    if (threadIdx.x == 1023) bsum[blockIdx.x] = sh[1023];
}

__global__ void scan2_k(int* __restrict__ bsumA, int nb) {
    int* bsum = bsumA + blockIdx.x * 64;
    __shared__ int sh[64];
    int t = threadIdx.x;
    int v = (t < nb) ? bsum[t] : 0;
    sh[t] = v;
    __syncthreads();
    for (int d = 1; d < 64; d <<= 1) {
        int u = (t >= d) ? sh[t - d] : 0;
        __syncthreads();
        sh[t] += u;
        __syncthreads();
    }
    if (t < nb) bsum[t] = sh[t] - v;
}

__global__ void scan3_k(int* __restrict__ offA, const int* __restrict__ bsumA,
                        int* __restrict__ cursorA, int n) {
    int t = blockIdx.y;
    int gid = blockIdx.x * blockDim.x + threadIdx.x;
    if (gid < n) {
        int v = offA[t * n + gid] + bsumA[t * 64 + (gid >> 10)];
        offA[t * n + gid] = v;
        cursorA[t * n + gid] = v;
    }
}

__global__ void fill6_k(const int* __restrict__ ei, const float* __restrict__ disA,
                        int* __restrict__ cursorA, int* __restrict__ psrcA,
                        float* __restrict__ wsrcA, int e) {
    int t = blockIdx.y;
    int i = blockIdx.x * blockDim.x + threadIdx.x;
    if (i < e) {
        const int* src = ei + (size_t)t * 2 * e;
        const int* dst = src + e;
        const float* dis = disA + t * N_NODES;
        int s = src[i], d = dst[i];
        int pos = atomicAdd(&cursorA[t * N_NODES + d], 1);
        psrcA[(size_t)t * e + pos] = s;
        wsrcA[(size_t)t * e + pos] = dis[s] * dis[d];
    }
}

// ---------------- fused gather + epilogue kernels (one warp per node) -------
__global__ void gather_e1_k(const float* __restrict__ hw, const int* __restrict__ off,
                            const int* __restrict__ cnt, const int* __restrict__ psrc,
                            const float* __restrict__ wsrc,
                            const float* __restrict__ dis, const float* __restrict__ bias,
                            float* __restrict__ out, int n) {
    int warp = (blockIdx.x * blockDim.x + threadIdx.x) >> 5;
    int lane = threadIdx.x & 31;
    if (warp >= n) return;
    const int i = warp;
    const int o = off[i], c = cnt[i];
    const float4* hw4 = reinterpret_cast<const float4*>(hw);
    float4 acc = make_float4(0.f, 0.f, 0.f, 0.f);
    int k = 0;
    for (; k + 2 <= c; k += 2) {
        int s0 = psrc[o + k], s1 = psrc[o + k + 1];
        float w0 = wsrc[o + k], w1 = wsrc[o + k + 1];
        float4 h0 = hw4[(size_t)s0 * 32 + lane];
        float4 h1 = hw4[(size_t)s1 * 32 + lane];
        acc.x += w0 * h0.x + w1 * h1.x;
        acc.y += w0 * h0.y + w1 * h1.y;
        acc.z += w0 * h0.z + w1 * h1.z;
        acc.w += w0 * h0.w + w1 * h1.w;
    }
    if (k < c) {
        int s0 = psrc[o + k];
        float w0 = wsrc[o + k];
        float4 h0 = hw4[(size_t)s0 * 32 + lane];
        acc.x += w0 * h0.x; acc.y += w0 * h0.y; acc.z += w0 * h0.z; acc.w += w0 * h0.w;
    }
    const float di = dis[i];
    const float sn = di * di;
    float4 hs = hw4[(size_t)i * 32 + lane];
    float4 b = reinterpret_cast<const float4*>(bias)[lane];
    float4 r;
    r.x = fmaxf(acc.x + hs.x * sn + b.x, 0.f);
    r.y = fmaxf(acc.y + hs.y * sn + b.y, 0.f);
    r.z = fmaxf(acc.z + hs.z * sn + b.z, 0.f);
    r.w = fmaxf(acc.w + hs.w * sn + b.w, 0.f);
    reinterpret_cast<float4*>(out)[(size_t)i * 32 + lane] = r;
}

__global__ void gather_z_k(const float* __restrict__ hw, const int* __restrict__ off,
                           const int* __restrict__ cnt, const int* __restrict__ psrc,
                           const float* __restrict__ wsrc,
                           const float* __restrict__ dis, const float* __restrict__ bias,
                           float* __restrict__ out, int n) {
    int warp = (blockIdx.x * blockDim.x + threadIdx.x) >> 5;
    int lane = threadIdx.x & 31;
    if (warp >= n) return;
    const int i = warp;
    const int o = off[i], c = cnt[i];
    const float2* hw2 = reinterpret_cast<const float2*>(hw);
    float2 acc = make_float2(0.f, 0.f);
    int k = 0;
    for (; k + 2 <= c; k += 2) {
        int s0 = psrc[o + k], s1 = psrc[o + k + 1];
        float w0 = wsrc[o + k], w1 = wsrc[o + k + 1];
        float2 h0 = hw2[(size_t)s0 * 32 + lane];
        float2 h1 = hw2[(size_t)s1 * 32 + lane];
        acc.x += w0 * h0.x + w1 * h1.x;
        acc.y += w0 * h0.y + w1 * h1.y;
    }
    if (k < c) {
        int s0 = psrc[o + k];
        float w0 = wsrc[o + k];
        float2 h0 = hw2[(size_t)s0 * 32 + lane];
        acc.x += w0 * h0.x; acc.y += w0 * h0.y;
    }
    const float di = dis[i];
    const float sn = di * di;
    float2 hs = hw2[(size_t)i * 32 + lane];
    float2 b = reinterpret_cast<const float2*>(bias)[lane];
    float2 r;
    r.x = acc.x + hs.x * sn + b.x;
    r.y = acc.y + hs.y * sn + b.y;
    reinterpret_cast<float2*>(out)[(size_t)i * 32 + lane] = r;
}

__device__ __forceinline__ float sigf(float v) { return 1.0f / (1.0f + __expf(-v)); }

__global__ void gather_gates_k(const float* __restrict__ uz, const float* __restrict__ ur,
                               const float* __restrict__ uh,
                               const int* __restrict__ off, const int* __restrict__ cnt,
                               const int* __restrict__ psrc, const float* __restrict__ wsrc,
                               const float* __restrict__ dis,
                               const float* __restrict__ bxz, const float* __restrict__ bhz,
                               const float* __restrict__ bxr, const float* __restrict__ bhr,
                               const float* __restrict__ bxh, const float* __restrict__ hold,
                               float* __restrict__ zg, float* __restrict__ ph,
                               float* __restrict__ rh, int n) {
    int warp = (blockIdx.x * blockDim.x + threadIdx.x) >> 5;
    int lane = threadIdx.x & 31;
    if (warp >= n) return;
    const int i = warp;
    const int o = off[i], c = cnt[i];
    const float4* z4 = reinterpret_cast<const float4*>(uz);
    const float4* r4 = reinterpret_cast<const float4*>(ur);
    const float4* h4 = reinterpret_cast<const float4*>(uh);
    float4 az = make_float4(0.f, 0.f, 0.f, 0.f);
    float4 ar = make_float4(0.f, 0.f, 0.f, 0.f);
    float4 ah = make_float4(0.f, 0.f, 0.f, 0.f);
    int k = 0;
    for (; k + 2 <= c; k += 2) {
        int s0 = psrc[o + k], s1 = psrc[o + k + 1];
        float w0 = wsrc[o + k], w1 = wsrc[o + k + 1];
        size_t b0 = (size_t)s0 * 32 + lane;
        size_t b1 = (size_t)s1 * 32 + lane;
        float4 vz0 = z4[b0], vr0 = r4[b0], vh0 = h4[b0];
        float4 vz1 = z4[b1], vr1 = r4[b1], vh1 = h4[b1];
        az.x += w0 * vz0.x + w1 * vz1.x; az.y += w0 * vz0.y + w1 * vz1.y;
        az.z += w0 * vz0.z + w1 * vz1.z; az.w += w0 * vz0.w + w1 * vz1.w;
        ar.x += w0 * vr0.x + w1 * vr1.x; ar.y += w0 * vr0.y + w1 * vr1.y;
        ar.z += w0 * vr0.z + w1 * vr1.z; ar.w += w0 * vr0.w + w1 * vr1.w;
        ah.x += w0 * vh0.x + w1 * vh1.x; ah.y += w0 * vh0.y + w1 * vh1.y;
        ah.z += w0 * vh0.z + w1 * vh1.z; ah.w += w0 * vh0.w + w1 * vh1.w;
    }
    if (k < c) {
        int s = psrc[o + k];
        float w = wsrc[o + k];
        size_t sb = (size_t)s * 32 + lane;
        float4 vz = z4[sb], vr = r4[sb], vh = h4[sb];
        az.x += w * vz.x; az.y += w * vz.y; az.z += w * vz.z; az.w += w * vz.w;
        ar.x += w * vr.x; ar.y += w * vr.y; ar.z += w * vr.z; ar.w += w * vr.w;
        ah.x += w * vh.x; ah.y += w * vh.y; ah.z += w * vh.z; ah.w += w * vh.w;
    }
    const float di = dis[i];
    const float sn = di * di;
    size_t ib = (size_t)i * 32 + lane;
    float4 sz = z4[ib], sr = r4[ib], sh = h4[ib];
    float4 B_xz = reinterpret_cast<const float4*>(bxz)[lane];
    float4 B_hz = reinterpret_cast<const float4*>(bhz)[lane];
    float4 B_xr = reinterpret_cast<const float4*>(bxr)[lane];
    float4 B_hr = reinterpret_cast<const float4*>(bhr)[lane];
    float4 B_xh = reinterpret_cast<const float4*>(bxh)[lane];
    float4 hv = reinterpret_cast<const float4*>(hold)[ib];
    float4 zo, po, ro;
    zo.x = sigf(az.x + sz.x * sn + B_xz.x + B_hz.x);
    zo.y = sigf(az.y + sz.y * sn + B_xz.y + B_hz.y);
    zo.z = sigf(az.z + sz.z * sn + B_xz.z + B_hz.z);
    zo.w = sigf(az.w + sz.w * sn + B_xz.w + B_hz.w);
    float rx = sigf(ar.x + sr.x * sn + B_xr.x + B_hr.x);
    float ry = sigf(ar.y + sr.y * sn + B_xr.y + B_hr.y);
    float rz = sigf(ar.z + sr.z * sn + B_xr.z + B_hr.z);
    float rw = sigf(ar.w + sr.w * sn + B_xr.w + B_hr.w);
    po.x = ah.x + sh.x * sn + B_xh.x;
    po.y = ah.y + sh.y * sn + B_xh.y;
    po.z = ah.z + sh.z * sn + B_xh.z;
    po.w = ah.w + sh.w * sn + B_xh.w;
    ro.x = rx * hv.x; ro.y = ry * hv.y; ro.z = rz * hv.z; ro.w = rw * hv.w;
    reinterpret_cast<float4*>(zg)[ib] = zo;
    reinterpret_cast<float4*>(ph)[ib] = po;
    reinterpret_cast<float4*>(rh)[ib] = ro;
}

__global__ void gather_hup_k(const float* __restrict__ vb, const int* __restrict__ off,
                             const int* __restrict__ cnt, const int* __restrict__ psrc,
                             const float* __restrict__ wsrc,
                             const float* __restrict__ dis, const float* __restrict__ bhh,
                             const float* __restrict__ ph, const float* __restrict__ zg,
                             const float* __restrict__ hold, float* __restrict__ hnew, int n) {
    int warp = (blockIdx.x * blockDim.x + threadIdx.x) >> 5;
    int lane = threadIdx.x & 31;
    if (warp >= n) return;
    const int i = warp;
    const int o = off[i], c = cnt[i];
    const float4* v4 = reinterpret_cast<const float4*>(vb);
    float4 acc = make_float4(0.f, 0.f, 0.f, 0.f);
    int k = 0;
    for (; k + 2 <= c; k += 2) {
        int s0 = psrc[o + k], s1 = psrc[o + k + 1];
        float w0 = wsrc[o + k], w1 = wsrc[o + k + 1];
        float4 h0 = v4[(size_t)s0 * 32 + lane];
        float4 h1 = v4[(size_t)s1 * 32 + lane];
        acc.x += w0 * h0.x + w1 * h1.x;
        acc.y += w0 * h0.y + w1 * h1.y;
        acc.z += w0 * h0.z + w1 * h1.z;
        acc.w += w0 * h0.w + w1 * h1.w;
    }
    if (k < c) {
        int s0 = psrc[o + k];
        float w0 = wsrc[o + k];
        float4 h0 = v4[(size_t)s0 * 32 + lane];
        acc.x += w0 * h0.x; acc.y += w0 * h0.y; acc.z += w0 * h0.z; acc.w += w0 * h0.w;
    }
    const float di = dis[i];
    const float sn = di * di;
    size_t ib = (size_t)i * 32 + lane;
    float4 vs = v4[ib];
    float4 B = reinterpret_cast<const float4*>(bhh)[lane];
    float4 pv = reinterpret_cast<const float4*>(ph)[ib];
    float4 zv = reinterpret_cast<const float4*>(zg)[ib];
    float4 h0r = reinterpret_cast<const float4*>(hold)[lane];
    float4 r;
    float hhx = tanhf(pv.x + acc.x + vs.x * sn + B.x);
    float hhy = tanhf(pv.y + acc.y + vs.y * sn + B.y);
    float hhz = tanhf(pv.z + acc.z + vs.z * sn + B.z);
    float hhw = tanhf(pv.w + acc.w + vs.w * sn + B.w);
    r.x = zv.x * h0r.x + (1.0f - zv.x) * hhx;
    r.y = zv.y * h0r.y + (1.0f - zv.y) * hhy;
    r.z = zv.z * h0r.z + (1.0f - zv.z) * hhz;
    r.w = zv.w * h0r.w + (1.0f - zv.w) * hhw;
    reinterpret_cast<float4*>(hnew)[ib] = r;
}

// ---------------- host-side GEMM wrappers ----------------
static constexpr int SMEM_FK(int F, int K) {
    return (64 * (K + 8) + F * (K + 8)) * 2 * 2;  // (A + W) x (hi+lo) bf16
}

extern "C" void kernel_launch(void* const* d_in, const int* in_sizes, int n_in,
                              void* d_out, int out_size) {
    (void)in_sizes; (void)n_in; (void)out_size;
    const float* x   = (const float*)d_in[0];
    const int*   ei  = (const int*)d_in[1];
    const float* Wpx = (const float*)d_in[2];  const float* bpx = (const float*)d_in[3];
    // d_in[4..9] dead (prior MLPs)
    const float* Wc1 = (const float*)d_in[10]; const float* bc1 = (const float*)d_in[11];
    const float* Wm  = (const float*)d_in[12]; const float* bm  = (const float*)d_in[13];
    const float* Wpz = (const float*)d_in[14]; const float* bpz = (const float*)d_in[15];
    const float* Wxz = (const float*)d_in[16]; const float* bxz = (const float*)d_in[17];
    const float* Whz = (const float*)d_in[18]; const float* bhz = (const float*)d_in[19];
    const float* Wxr = (const float*)d_in[20]; const float* bxr = (const float*)d_in[21];
    const float* Whr = (const float*)d_in[22]; const float* bhr = (const float*)d_in[23];
    const float* Wxh = (const float*)d_in[24]; const float* bxh = (const float*)d_in[25];
    const float* Whh = (const float*)d_in[26]; const float* bhh = (const float*)d_in[27];
    float* out = (float*)d_out;

    cudaFuncSetAttribute(tcgemm_k<128, 128>, cudaFuncAttributeMaxDynamicSharedMemorySize, SMEM_FK(128, 128));
    cudaFuncSetAttribute(tcgemm_k<64, 128>,  cudaFuncAttributeMaxDynamicSharedMemorySize, SMEM_FK(64, 128));
    cudaFuncSetAttribute(tcgemm_k<128, 64>,  cudaFuncAttributeMaxDynamicSharedMemorySize, SMEM_FK(128, 64));
    cudaFuncSetAttribute(tcgemm2_k,          cudaFuncAttributeMaxDynamicSharedMemorySize, SMEM_FK(128, 128));

    float* base = nullptr;
    cudaGetSymbolAddress((void**)&base, g_scratch);
    __nv_bfloat16* whi = nullptr;
    cudaGetSymbolAddress((void**)&whi, g_wbf);
    const int WTOT = 212992;
    __nv_bfloat16* wlo = whi + WTOT;

    const size_t NB = 6400000ull;   // N*128
    const size_t NZ = 3200000ull;   // N*64
    float* xp    = base + 0 * NB;
    float* hbuf0 = base + 1 * NB;
    float* hbuf1 = base + 2 * NB;
    float* hw1   = base + 3 * NB;
    float* e1    = base + 4 * NB;
    float* zp    = base + 5 * NB;
    float* uz    = base + 6 * NB;
    float* ur    = base + 7 * NB;
    float* uh    = base + 8 * NB;
    float* zgb   = base + 9 * NB;
    float* phb   = base + 10 * NB;
    float* rhb   = base + 11 * NB;
    float* vb    = base + 12 * NB;
    float* pc1   = base + 13 * NB;
    float* pxz   = base + 14 * NB;
    float* pxr   = base + 15 * NB;
    float* pxh   = base + 16 * NB;
    float* hw2   = base + 17 * NB;           // N*64
    // batched CSR arrays (6 timesteps)
    float* disA  = hw2 + NZ;                         // 6N
    int*   cntA    = (int*)(disA + 6 * N_NODES);     // 6N
    int*   offA    = cntA + 6 * N_NODES;             // 6N
    int*   cursorA = offA + 6 * N_NODES;             // 6N
    int*   bsumA   = cursorA + 6 * N_NODES;          // 6*64
    int*   psrcA   = bsumA + 6 * 64;                 // 6E
    float* wsrcA   = (float*)(psrcA + 6 * N_EDGES);  // 6E

    // weight table: 0..11 are [128,128], 12 = Wm [128,64], 13 = Wpz [64,128]
    WCvtTab tab;
    const int S = 128 * 128;
    tab.m[0]  = {Wpx,     128, 128, 0 * S};
    tab.m[1]  = {Wc1,     128, 128, 1 * S};   // top half
    tab.m[2]  = {Wc1 + S, 128, 128, 2 * S};   // bottom half
    tab.m[3]  = {Wxz,     128, 128, 3 * S};
    tab.m[4]  = {Wxz + S, 128, 128, 4 * S};
    tab.m[5]  = {Whz,     128, 128, 5 * S};
    tab.m[6]  = {Wxr,     128, 128, 6 * S};
    tab.m[7]  = {Wxr + S, 128, 128, 7 * S};
    tab.m[8]  = {Whr,     128, 128, 8 * S};
    tab.m[9]  = {Wxh,     128, 128, 9 * S};
    tab.m[10] = {Wxh + S, 128, 128, 10 * S};
    tab.m[11] = {Whh,     128, 128, 11 * S};
    tab.m[12] = {Wm,      128, 64,  12 * S};
    tab.m[13] = {Wpz,     64,  128, 12 * S + 8192};

    const int N = N_NODES, E = N_EDGES;
    dim3 b256(256);
    const int gE = (E + 255) / 256;
    const int gN = (N + 255) / 256;
    const int gW = (N * 32 + 255) / 256;
    const int nScanBlocks = (N + 1023) / 1024;
    const int gG = (N + 63) / 64;   // GEMM grid (BM=64)

    float* hb[2] = {hbuf0, hbuf1};

    cudaMemsetAsync(hb[0], 0, NB * sizeof(float));

    // preconvert all weights once
    convw_k<<<dim3(64, 14), b256>>>(tab, whi, wlo);

    // ---- batched CSR build for all 6 timesteps ----
    cudaMemsetAsync(cntA, 0, 6 * N * sizeof(int));
    count6_k<<<dim3(gE, 6), b256>>>(ei, cntA, E);
    dis6_k<<<dim3(gN, 6), b256>>>(cntA, disA, N);
    scan1_k<<<dim3(nScanBlocks, 6), 1024>>>(cntA, offA, bsumA, N);
    scan2_k<<<6, 64>>>(bsumA, nScanBlocks);
    scan3_k<<<dim3(gN, 6), b256>>>(offA, bsumA, cursorA, N);
    fill6_k<<<dim3(gE, 6), b256>>>(ei, disA, cursorA, psrcA, wsrcA, E);

    auto WH = [&](int m) { return whi + tab.m[m].off; };
    auto WL = [&](int m) { return wlo + tab.m[m].off; };

#define G128(Ap, m, Cp, Cadd, bias, act) \
    tcgemm_k<128, 128><<<gG, 256, SMEM_FK(128, 128)>>>(Ap, WH(m), WL(m), Cp, N, Cadd, bias, act)

    // time-invariant precomputes
    G128(x, 0, xp, nullptr, bpx, 1);
    G128(xp, 1, pc1, nullptr, nullptr, 0);
    G128(xp, 3, pxz, nullptr, nullptr, 0);
    G128(xp, 6, pxr, nullptr, nullptr, 0);
    G128(xp, 9, pxh, nullptr, nullptr, 0);

    for (int t = 0; t < T_STEPS; t++) {
        float* hold = hb[t & 1];
        float* hnew = (t == T_STEPS - 1) ? (out + (size_t)T_STEPS * NZ) : hb[(t + 1) & 1];
        float* zt = out + (size_t)t * NZ;
        const int*   off  = offA + t * N;
        const int*   cnt  = cntA + t * N;
        const int*   psrc = psrcA + (size_t)t * E;
        const float* wsrc = wsrcA + (size_t)t * E;
        const float* dis  = disA + t * N;

        // ---- e1 = relu(gcn(concat(xp,h) @ Wc1)) ----
        G128(hold, 2, hw1, pc1, nullptr, 0);
        gather_e1_k<<<gW, b256>>>(hw1, off, cnt, psrc, wsrc, dis, bc1, e1, N);

        // ---- z = gcn(e1 @ Wm) -> out slot t ----
        tcgemm_k<64, 128><<<gG, 256, SMEM_FK(64, 128)>>>(e1, WH(12), WL(12), hw2, N,
                                                         nullptr, nullptr, 0);
        gather_z_k<<<gW, b256>>>(hw2, off, cnt, psrc, wsrc, dis, bm, zt, N);

        // ---- zp = relu(z @ Wpz + bpz) ----
        tcgemm_k<128, 64><<<gG, 256, SMEM_FK(128, 64)>>>(zt, WH(13), WL(13), zp, N,
                                                         nullptr, bpz, 1);

        // ---- fused GRU linears ----
        tcgemm2_k<<<gG, 256, SMEM_FK(128, 128)>>>(zp, WH(4), WL(4), hold, WH(5), WL(5),
                                                  uz, N, pxz);
        tcgemm2_k<<<gG, 256, SMEM_FK(128, 128)>>>(zp, WH(7), WL(7), hold, WH(8), WL(8),
                                                  ur, N, pxr);
        G128(zp, 10, uh, pxh, nullptr, 0);

        // ---- triple gather + gates ----
        gather_gates_k<<<gW, b256>>>(uz, ur, uh, off, cnt, psrc, wsrc, dis,
                                     bxz, bhz, bxr, bhr, bxh, hold,
                                     zgb, phb, rhb, N);

        // ---- v = (rg*h) @ Whh ; gather + h update ----
        G128(rhb, 11, vb, nullptr, nullptr, 0);
        gather_hup_k<<<gW, b256>>>(vb, off, cnt, psrc, wsrc, dis, bhh, phb, zgb, hold, hnew, N);
    }
#undef G128
}

// round 13
// speedup vs baseline: 1.3417x; 1.3417x over previous
#include <cuda_runtime.h>
#include <cuda_bf16.h>
#include <cstdint>
#include <cstddef>

// ---------------- problem constants ----------------
#define N_NODES 50000
#define N_EDGES 800000
#define T_STEPS 6

__device__ float g_scratch[115000000];
// preconverted weights: 14 matrices, 212992 elements, hi + lo
__device__ __nv_bfloat16 g_wbf[425984];

// ============================================================================
// Weight pre-conversion: fp32 W[K,F] -> bf16 hi/lo, transposed to [F][K]
// ============================================================================
struct WCvt { const float* w; int K; int F; int off; };
struct WCvtTab { WCvt m[14]; };

__global__ void convw_k(WCvtTab tab, __nv_bfloat16* __restrict__ hi,
                        __nv_bfloat16* __restrict__ lo) {
    WCvt d = tab.m[blockIdx.y];
    int idx = blockIdx.x * 256 + threadIdx.x;
    if (idx >= d.K * d.F) return;
    int f = idx / d.K, k = idx % d.K;
    float v = d.w[(size_t)k * d.F + f];
    __nv_bfloat16 h = __float2bfloat16(v);
    hi[d.off + idx] = h;
    lo[d.off + idx] = __float2bfloat16(v - __bfloat162float(h));
}

// ============================================================================
// bf16-split tensor-core GEMM via mma.sync + ldmatrix (round-9 configuration)
// ============================================================================
__device__ __forceinline__ void mma16816(float* c, uint32_t a0, uint32_t a1,
                                         uint32_t a2, uint32_t a3,
                                         uint32_t b0, uint32_t b1) {
    asm volatile(
        "mma.sync.aligned.m16n8k16.row.col.f32.bf16.bf16.f32 "
        "{%0,%1,%2,%3}, {%4,%5,%6,%7}, {%8,%9}, {%0,%1,%2,%3};"
        : "+f"(c[0]), "+f"(c[1]), "+f"(c[2]), "+f"(c[3])
        : "r"(a0), "r"(a1), "r"(a2), "r"(a3), "r"(b0), "r"(b1));
}

__device__ __forceinline__ void ldsm_x4(uint32_t& r0, uint32_t& r1, uint32_t& r2,
                                        uint32_t& r3, uint32_t addr) {
    asm volatile("ldmatrix.sync.aligned.m8n8.x4.shared.b16 {%0,%1,%2,%3}, [%4];"
                 : "=r"(r0), "=r"(r1), "=r"(r2), "=r"(r3) : "r"(addr));
}

__device__ __forceinline__ uint32_t smem_u32(const void* p) {
    uint32_t a;
    asm("{ .reg .u64 t; cvta.to.shared.u64 t, %1; cvt.u32.u64 %0, t; }" : "=r"(a) : "l"(p));
    return a;
}

#define CP_ASYNC16(smem_addr, gptr) \
    asm volatile("cp.async.cg.shared.global [%0], [%1], 16;" \
                 :: "r"(smem_addr), "l"(gptr))
#define CP_ASYNC_COMMIT() asm volatile("cp.async.commit_group;" ::: "memory")
#define CP_ASYNC_WAIT0()  asm volatile("cp.async.wait_group 0;" ::: "memory")

template <int BM, int K>
__device__ __forceinline__ void load_a_tile(const float* __restrict__ A, int bm, int M,
                                            uint16_t* Ah, uint16_t* Al, int tid) {
    constexpr int SK = K + 8;
    for (int i = tid * 4; i < BM * K; i += 256 * 4) {
        int row = i / K;
        int k = i % K;
        int g = bm + row;
        float4 v = make_float4(0.f, 0.f, 0.f, 0.f);
        if (g < M) v = *reinterpret_cast<const float4*>(A + (size_t)g * K + k);
        float2 p0 = make_float2(v.x, v.y);
        float2 p1 = make_float2(v.z, v.w);
        __nv_bfloat162 h0 = __float22bfloat162_rn(p0);
        __nv_bfloat162 h1 = __float22bfloat162_rn(p1);
        float2 b0 = __bfloat1622float2(h0);
        float2 b1 = __bfloat1622float2(h1);
        __nv_bfloat162 l0 = __float22bfloat162_rn(make_float2(p0.x - b0.x, p0.y - b0.y));
        __nv_bfloat162 l1 = __float22bfloat162_rn(make_float2(p1.x - b1.x, p1.y - b1.y));
        uint2 hv, lv;
        hv.x = *reinterpret_cast<uint32_t*>(&h0);
        hv.y = *reinterpret_cast<uint32_t*>(&h1);
        lv.x = *reinterpret_cast<uint32_t*>(&l0);
        lv.y = *reinterpret_cast<uint32_t*>(&l1);
        *reinterpret_cast<uint2*>(Ah + row * SK + k) = hv;
        *reinterpret_cast<uint2*>(Al + row * SK + k) = lv;
    }
}

template <int F, int K>
__device__ __forceinline__ void issue_w_copy(const __nv_bfloat16* __restrict__ Whi,
                                             const __nv_bfloat16* __restrict__ Wlo,
                                             uint16_t* Wh, uint16_t* Wl, int tid) {
    constexpr int SK = K + 8;
    for (int i = tid; i < F * (K / 8); i += 256) {
        int row = i / (K / 8);
        int kc = (i % (K / 8)) * 8;
        CP_ASYNC16(smem_u32(Wh + row * SK + kc), Whi + (size_t)row * K + kc);
        CP_ASYNC16(smem_u32(Wl + row * SK + kc), Wlo + (size_t)row * K + kc);
    }
    CP_ASYNC_COMMIT();
}

template <int MFR, int NPAIR, int KSTEPS>
__device__ __forceinline__ void mainloop(const uint16_t* Ah, const uint16_t* Al,
                                         const uint16_t* Wh, const uint16_t* Wl,
                                         const int* a_off, const int* b_off,
                                         float (*acc)[4]) {
    const uint16_t* Asel[3] = {Ah, Ah, Al};
    const uint16_t* Bsel[3] = {Wh, Wl, Wh};
#pragma unroll
    for (int p = 0; p < 3; p++) {
        const uint32_t abase = smem_u32(Asel[p]);
        const uint32_t bbase = smem_u32(Bsel[p]);
#pragma unroll
        for (int ks = 0; ks < KSTEPS; ks++) {
            uint32_t af[MFR][4];
#pragma unroll
            for (int mi = 0; mi < MFR; mi++)
                ldsm_x4(af[mi][0], af[mi][1], af[mi][2], af[mi][3],
                        abase + a_off[mi] + ks * 32);
            uint32_t bf[NPAIR][4];
#pragma unroll
            for (int pr = 0; pr < NPAIR; pr++)
                ldsm_x4(bf[pr][0], bf[pr][1], bf[pr][2], bf[pr][3],
                        bbase + b_off[pr] + ks * 32);
#pragma unroll
            for (int pr = 0; pr < NPAIR; pr++)
#pragma unroll
                for (int half = 0; half < 2; half++) {
                    uint32_t b0 = bf[pr][half * 2 + 0];
                    uint32_t b1 = bf[pr][half * 2 + 1];
#pragma unroll
                    for (int mi = 0; mi < MFR; mi++)
                        mma16816(acc[mi * NPAIR * 2 + pr * 2 + half],
                                 af[mi][0], af[mi][1], af[mi][2], af[mi][3], b0, b1);
                }
        }
    }
}

template <int F, int K>
__global__ void __launch_bounds__(256, 2)
tcgemm_k(const float* __restrict__ A,
         const __nv_bfloat16* __restrict__ Whi, const __nv_bfloat16* __restrict__ Wlo,
         float* __restrict__ C, int M,
         const float* __restrict__ Cadd, const float* __restrict__ bias, int act) {
    constexpr int BM = 64;
    constexpr int SK = K + 8;
    constexpr int WARPS_N = F / 32;
    constexpr int WARPS_M = 8 / WARPS_N;
    constexpr int WTM = BM / WARPS_M;
    constexpr int MFR = WTM / 16;
    constexpr int NFR = 4;
    constexpr int NPAIR = NFR / 2;
    constexpr int KSTEPS = K / 16;

    extern __shared__ char sm[];
    uint16_t* Ah = reinterpret_cast<uint16_t*>(sm);
    uint16_t* Al = Ah + BM * SK;
    uint16_t* Wh = Al + BM * SK;
    uint16_t* Wl = Wh + F * SK;

    const int tid = threadIdx.x;
    const int warp = tid >> 5;
    const int lane = tid & 31;
    const int bm = blockIdx.x * BM;
    const int wm = warp % WARPS_M;
    const int wn = warp / WARPS_M;
    const int rb = wm * WTM;
    const int cb = wn * 32;

    issue_w_copy<F, K>(Whi, Wlo, Wh, Wl, tid);
    load_a_tile<BM, K>(A, bm, M, Ah, Al, tid);
    CP_ASYNC_WAIT0();
    __syncthreads();

    float acc[MFR * NFR][4];
#pragma unroll
    for (int q = 0; q < MFR * NFR; q++) {
        acc[q][0] = 0.f; acc[q][1] = 0.f; acc[q][2] = 0.f; acc[q][3] = 0.f;
    }

    int a_off[MFR], b_off[NPAIR];
#pragma unroll
    for (int mi = 0; mi < MFR; mi++)
        a_off[mi] = ((rb + mi * 16 + (lane & 7) + ((lane >> 3) & 1) * 8) * SK +
                     ((lane >> 4) & 1) * 8) * 2;
#pragma unroll
    for (int pr = 0; pr < NPAIR; pr++)
        b_off[pr] = ((cb + pr * 16 + ((lane >> 4) & 1) * 8 + (lane & 7)) * SK +
                     ((lane >> 3) & 1) * 8) * 2;

    mainloop<MFR, NPAIR, KSTEPS>(Ah, Al, Wh, Wl, a_off, b_off, acc);

    const int gq = lane >> 2;
    const int tq = lane & 3;
#pragma unroll
    for (int mi = 0; mi < MFR; mi++) {
#pragma unroll
        for (int half = 0; half < 2; half++) {
            int gr = bm + rb + mi * 16 + gq + half * 8;
            if (gr >= M) continue;
#pragma unroll
            for (int ni = 0; ni < NFR; ni++) {
                int gc = cb + ni * 8 + tq * 2;
                float v0 = acc[mi * NFR + ni][half * 2 + 0];
                float v1 = acc[mi * NFR + ni][half * 2 + 1];
                if (Cadd) {
                    float2 a = *reinterpret_cast<const float2*>(Cadd + (size_t)gr * F + gc);
                    v0 += a.x; v1 += a.y;
                }
                if (bias) {
                    float2 b = *reinterpret_cast<const float2*>(bias + gc);
                    v0 += b.x; v1 += b.y;
                }
                if (act) { v0 = fmaxf(v0, 0.f); v1 = fmaxf(v1, 0.f); }
                float2 o; o.x = v0; o.y = v1;
                *reinterpret_cast<float2*>(C + (size_t)gr * F + gc) = o;
            }
        }
    }
}

// fused dual-(A,W): C = A1@W1 + A2@W2 + Cadd  (F=128, K=128), 2-phase SMEM reuse
__global__ void __launch_bounds__(256, 2)
tcgemm2_k(const float* __restrict__ A1,
          const __nv_bfloat16* __restrict__ W1h, const __nv_bfloat16* __restrict__ W1l,
          const float* __restrict__ A2,
          const __nv_bfloat16* __restrict__ W2h, const __nv_bfloat16* __restrict__ W2l,
          float* __restrict__ C, int M, const float* __restrict__ Cadd) {
    constexpr int F = 128, K = 128, BM = 64;
    constexpr int SK = K + 8;
    constexpr int WARPS_M = 2;
    constexpr int KSTEPS = 8;

    extern __shared__ char sm[];
    uint16_t* Ah = reinterpret_cast<uint16_t*>(sm);
    uint16_t* Al = Ah + BM * SK;
    uint16_t* Wh = Al + BM * SK;
    uint16_t* Wl = Wh + F * SK;

    const int tid = threadIdx.x;
    const int warp = tid >> 5;
    const int lane = tid & 31;
    const int bm = blockIdx.x * BM;
    const int wm = warp % WARPS_M;
    const int wn = warp / WARPS_M;
    const int rb = wm * 32;
    const int cb = wn * 32;

    float acc[8][4];
#pragma unroll
    for (int q = 0; q < 8; q++) {
        acc[q][0] = 0.f; acc[q][1] = 0.f; acc[q][2] = 0.f; acc[q][3] = 0.f;
    }

    int a_off[2], b_off[2];
#pragma unroll
    for (int mi = 0; mi < 2; mi++)
        a_off[mi] = ((rb + mi * 16 + (lane & 7) + ((lane >> 3) & 1) * 8) * SK +
                     ((lane >> 4) & 1) * 8) * 2;
#pragma unroll
    for (int pr = 0; pr < 2; pr++)
        b_off[pr] = ((cb + pr * 16 + ((lane >> 4) & 1) * 8 + (lane & 7)) * SK +
                     ((lane >> 3) & 1) * 8) * 2;

#pragma unroll
    for (int seg = 0; seg < 2; seg++) {
        if (seg) __syncthreads();
        const float* A = seg ? A2 : A1;
        const __nv_bfloat16* whi = seg ? W2h : W1h;
        const __nv_bfloat16* wlo = seg ? W2l : W1l;
        issue_w_copy<F, K>(whi, wlo, Wh, Wl, tid);
        load_a_tile<BM, K>(A, bm, M, Ah, Al, tid);
        CP_ASYNC_WAIT0();
        __syncthreads();
        mainloop<2, 2, KSTEPS>(Ah, Al, Wh, Wl, a_off, b_off, acc);
    }

    const int gq = lane >> 2;
    const int tq = lane & 3;
#pragma unroll
    for (int mi = 0; mi < 2; mi++) {
#pragma unroll
        for (int half = 0; half < 2; half++) {
            int gr = bm + rb + mi * 16 + gq + half * 8;
            if (gr >= M) continue;
#pragma unroll
            for (int ni = 0; ni < 4; ni++) {
                int gc = cb + ni * 8 + tq * 2;
                float v0 = acc[mi * 4 + ni][half * 2 + 0];
                float v1 = acc[mi * 4 + ni][half * 2 + 1];
                float2 a = *reinterpret_cast<const float2*>(Cadd + (size_t)gr * F + gc);
                v0 += a.x; v1 += a.y;
                float2 o; o.x = v0; o.y = v1;
                *reinterpret_cast<float2*>(C + (size_t)gr * F + gc) = o;
            }
        }
    }
}

// ---------------- CSR build kernels (per timestep, locality-preserving) -----
__global__ void count_k(const int* __restrict__ dst, int* __restrict__ cnt, int e) {
    int i = blockIdx.x * blockDim.x + threadIdx.x;
    if (i < e) atomicAdd(&cnt[dst[i]], 1);
}

// scan1 also produces dis = rsqrt(1 + cnt)
__global__ void scan1_k(const int* __restrict__ cnt, int* __restrict__ off,
                        int* __restrict__ bsum, float* __restrict__ dis, int n) {
    __shared__ int sh[1024];
    int gid = blockIdx.x * 1024 + threadIdx.x;
    int v = (gid < n) ? cnt[gid] : 0;
    if (gid < n) dis[gid] = rsqrtf(1.0f + (float)v);
    sh[threadIdx.x] = v;
    __syncthreads();
    for (int d = 1; d < 1024; d <<= 1) {
        int u = (threadIdx.x >= d) ? sh[threadIdx.x - d] : 0;
        __syncthreads();
        sh[threadIdx.x] += u;
        __syncthreads();
    }
    if (gid < n) off[gid] = sh[threadIdx.x] - v;
    if (threadIdx.x == 1023) bsum[blockIdx.x] = sh[1023];
}

__global__ void scan2_k(int* __restrict__ bsum, int nb) {
    __shared__ int sh[64];
    int t = threadIdx.x;
    int v = (t < nb) ? bsum[t] : 0;
    sh[t] = v;
    __syncthreads();
    for (int d = 1; d < 64; d <<= 1) {
        int u = (t >= d) ? sh[t - d] : 0;
        __syncthreads();
        sh[t] += u;
        __syncthreads();
    }
    if (t < nb) bsum[t] = sh[t] - v;
}

__global__ void scan3_k(int* __restrict__ off, const int* __restrict__ bsum,
                        int* __restrict__ cursor, int n) {
    int gid = blockIdx.x * blockDim.x + threadIdx.x;
    if (gid < n) {
        int v = off[gid] + bsum[gid >> 10];
        off[gid] = v;
        cursor[gid] = v;
    }
}

__global__ void fill_k(const int* __restrict__ src, const int* __restrict__ dst,
                       const float* __restrict__ dis, int* __restrict__ cursor,
                       int* __restrict__ psrc, float* __restrict__ wsrc, int e) {
    int i = blockIdx.x * blockDim.x + threadIdx.x;
    if (i < e) {
        int s = src[i], d = dst[i];
        int pos = atomicAdd(&cursor[d], 1);
        psrc[pos] = s;
        wsrc[pos] = dis[s] * dis[d];
    }
}

// ---------------- fused gather + epilogue kernels (one warp per node) -------
__global__ void gather_e1_k(const float* __restrict__ hw, const int* __restrict__ off,
                            const int* __restrict__ cnt, const int* __restrict__ psrc,
                            const float* __restrict__ wsrc,
                            const float* __restrict__ dis, const float* __restrict__ bias,
                            float* __restrict__ out, int n) {
    int warp = (blockIdx.x * blockDim.x + threadIdx.x) >> 5;
    int lane = threadIdx.x & 31;
    if (warp >= n) return;
    const int i = warp;
    const int o = off[i], c = cnt[i];
    const float4* hw4 = reinterpret_cast<const float4*>(hw);
    float4 acc = make_float4(0.f, 0.f, 0.f, 0.f);
    int k = 0;
    for (; k + 2 <= c; k += 2) {
        int s0 = psrc[o + k], s1 = psrc[o + k + 1];
        float w0 = wsrc[o + k], w1 = wsrc[o + k + 1];
        float4 h0 = hw4[(size_t)s0 * 32 + lane];
        float4 h1 = hw4[(size_t)s1 * 32 + lane];
        acc.x += w0 * h0.x + w1 * h1.x;
        acc.y += w0 * h0.y + w1 * h1.y;
        acc.z += w0 * h0.z + w1 * h1.z;
        acc.w += w0 * h0.w + w1 * h1.w;
    }
    if (k < c) {
        int s0 = psrc[o + k];
        float w0 = wsrc[o + k];
        float4 h0 = hw4[(size_t)s0 * 32 + lane];
        acc.x += w0 * h0.x; acc.y += w0 * h0.y; acc.z += w0 * h0.z; acc.w += w0 * h0.w;
    }
    const float di = dis[i];
    const float sn = di * di;
    float4 hs = hw4[(size_t)i * 32 + lane];
    float4 b = reinterpret_cast<const float4*>(bias)[lane];
    float4 r;
    r.x = fmaxf(acc.x + hs.x * sn + b.x, 0.f);
    r.y = fmaxf(acc.y + hs.y * sn + b.y, 0.f);
    r.z = fmaxf(acc.z + hs.z * sn + b.z, 0.f);
    r.w = fmaxf(acc.w + hs.w * sn + b.w, 0.f);
    reinterpret_cast<float4*>(out)[(size_t)i * 32 + lane] = r;
}

__global__ void gather_z_k(const float* __restrict__ hw, const int* __restrict__ off,
                           const int* __restrict__ cnt, const int* __restrict__ psrc,
                           const float* __restrict__ wsrc,
                           const float* __restrict__ dis, const float* __restrict__ bias,
                           float* __restrict__ out, int n) {
    int warp = (blockIdx.x * blockDim.x + threadIdx.x) >> 5;
    int lane = threadIdx.x & 31;
    if (warp >= n) return;
    const int i = warp;
    const int o = off[i], c = cnt[i];
    const float2* hw2 = reinterpret_cast<const float2*>(hw);
    float2 acc = make_float2(0.f, 0.f);
    int k = 0;
    for (; k + 2 <= c; k += 2) {
        int s0 = psrc[o + k], s1 = psrc[o + k + 1];
        float w0 = wsrc[o + k], w1 = wsrc[o + k + 1];
        float2 h0 = hw2[(size_t)s0 * 32 + lane];
        float2 h1 = hw2[(size_t)s1 * 32 + lane];
        acc.x += w0 * h0.x + w1 * h1.x;
        acc.y += w0 * h0.y + w1 * h1.y;
    }
    if (k < c) {
        int s0 = psrc[o + k];
        float w0 = wsrc[o + k];
        float2 h0 = hw2[(size_t)s0 * 32 + lane];
        acc.x += w0 * h0.x; acc.y += w0 * h0.y;
    }
    const float di = dis[i];
    const float sn = di * di;
    float2 hs = hw2[(size_t)i * 32 + lane];
    float2 b = reinterpret_cast<const float2*>(bias)[lane];
    float2 r;
    r.x = acc.x + hs.x * sn + b.x;
    r.y = acc.y + hs.y * sn + b.y;
    reinterpret_cast<float2*>(out)[(size_t)i * 32 + lane] = r;
}

__device__ __forceinline__ float sigf(float v) { return 1.0f / (1.0f + __expf(-v)); }

__global__ void gather_gates_k(const float* __restrict__ uz, const float* __restrict__ ur,
                               const float* __restrict__ uh,
                               const int* __restrict__ off, const int* __restrict__ cnt,
                               const int* __restrict__ psrc, const float* __restrict__ wsrc,
                               const float* __restrict__ dis,
                               const float* __restrict__ bxz, const float* __restrict__ bhz,
                               const float* __restrict__ bxr, const float* __restrict__ bhr,
                               const float* __restrict__ bxh, const float* __restrict__ hold,
                               float* __restrict__ zg, float* __restrict__ ph,
                               float* __restrict__ rh, int n) {
    int warp = (blockIdx.x * blockDim.x + threadIdx.x) >> 5;
    int lane = threadIdx.x & 31;
    if (warp >= n) return;
    const int i = warp;
    const int o = off[i], c = cnt[i];
    const float4* z4 = reinterpret_cast<const float4*>(uz);
    const float4* r4 = reinterpret_cast<const float4*>(ur);
    const float4* h4 = reinterpret_cast<const float4*>(uh);
    float4 az = make_float4(0.f, 0.f, 0.f, 0.f);
    float4 ar = make_float4(0.f, 0.f, 0.f, 0.f);
    float4 ah = make_float4(0.f, 0.f, 0.f, 0.f);
    int k = 0;
    for (; k + 2 <= c; k += 2) {
        int s0 = psrc[o + k], s1 = psrc[o + k + 1];
        float w0 = wsrc[o + k], w1 = wsrc[o + k + 1];
        size_t b0 = (size_t)s0 * 32 + lane;
        size_t b1 = (size_t)s1 * 32 + lane;
        float4 vz0 = z4[b0], vr0 = r4[b0], vh0 = h4[b0];
        float4 vz1 = z4[b1], vr1 = r4[b1], vh1 = h4[b1];
        az.x += w0 * vz0.x + w1 * vz1.x; az.y += w0 * vz0.y + w1 * vz1.y;
        az.z += w0 * vz0.z + w1 * vz1.z; az.w += w0 * vz0.w + w1 * vz1.w;
        ar.x += w0 * vr0.x + w1 * vr1.x; ar.y += w0 * vr0.y + w1 * vr1.y;
        ar.z += w0 * vr0.z + w1 * vr1.z; ar.w += w0 * vr0.w + w1 * vr1.w;
        ah.x += w0 * vh0.x + w1 * vh1.x; ah.y += w0 * vh0.y + w1 * vh1.y;
        ah.z += w0 * vh0.z + w1 * vh1.z; ah.w += w0 * vh0.w + w1 * vh1.w;
    }
    if (k < c) {
        int s = psrc[o + k];
        float w = wsrc[o + k];
        size_t sb = (size_t)s * 32 + lane;
        float4 vz = z4[sb], vr = r4[sb], vh = h4[sb];
        az.x += w * vz.x; az.y += w * vz.y; az.z += w * vz.z; az.w += w * vz.w;
        ar.x += w * vr.x; ar.y += w * vr.y; ar.z += w * vr.z; ar.w += w * vr.w;
        ah.x += w * vh.x; ah.y += w * vh.y; ah.z += w * vh.z; ah.w += w * vh.w;
    }
    const float di = dis[i];
    const float sn = di * di;
    size_t ib = (size_t)i * 32 + lane;
    float4 sz = z4[ib], sr = r4[ib], sh = h4[ib];
    float4 B_xz = reinterpret_cast<const float4*>(bxz)[lane];
    float4 B_hz = reinterpret_cast<const float4*>(bhz)[lane];
    float4 B_xr = reinterpret_cast<const float4*>(bxr)[lane];
    float4 B_hr = reinterpret_cast<const float4*>(bhr)[lane];
    float4 B_xh = reinterpret_cast<const float4*>(bxh)[lane];
    float4 hv = reinterpret_cast<const float4*>(hold)[ib];
    float4 zo, po, ro;
    zo.x = sigf(az.x + sz.x * sn + B_xz.x + B_hz.x);
    zo.y = sigf(az.y + sz.y * sn + B_xz.y + B_hz.y);
    zo.z = sigf(az.z + sz.z * sn + B_xz.z + B_hz.z);
    zo.w = sigf(az.w + sz.w * sn + B_xz.w + B_hz.w);
    float rx = sigf(ar.x + sr.x * sn + B_xr.x + B_hr.x);
    float ry = sigf(ar.y + sr.y * sn + B_xr.y + B_hr.y);
    float rz = sigf(ar.z + sr.z * sn + B_xr.z + B_hr.z);
    float rw = sigf(ar.w + sr.w * sn + B_xr.w + B_hr.w);
    po.x = ah.x + sh.x * sn + B_xh.x;
    po.y = ah.y + sh.y * sn + B_xh.y;
    po.z = ah.z + sh.z * sn + B_xh.z;
    po.w = ah.w + sh.w * sn + B_xh.w;
    ro.x = rx * hv.x; ro.y = ry * hv.y; ro.z = rz * hv.z; ro.w = rw * hv.w;
    reinterpret_cast<float4*>(zg)[ib] = zo;
    reinterpret_cast<float4*>(ph)[ib] = po;
    reinterpret_cast<float4*>(rh)[ib] = ro;
}

__global__ void gather_hup_k(const float* __restrict__ vb, const int* __restrict__ off,
                             const int* __restrict__ cnt, const int* __restrict__ psrc,
                             const float* __restrict__ wsrc,
                             const float* __restrict__ dis, const float* __restrict__ bhh,
                             const float* __restrict__ ph, const float* __restrict__ zg,
                             const float* __restrict__ hold, float* __restrict__ hnew, int n) {
    int warp = (blockIdx.x * blockDim.x + threadIdx.x) >> 5;
    int lane = threadIdx.x & 31;
    if (warp >= n) return;
    const int i = warp;
    const int o = off[i], c = cnt[i];
    const float4* v4 = reinterpret_cast<const float4*>(vb);
    float4 acc = make_float4(0.f, 0.f, 0.f, 0.f);
    int k = 0;
    for (; k + 2 <= c; k += 2) {
        int s0 = psrc[o + k], s1 = psrc[o + k + 1];
        float w0 = wsrc[o + k], w1 = wsrc[o + k + 1];
        float4 h0 = v4[(size_t)s0 * 32 + lane];
        float4 h1 = v4[(size_t)s1 * 32 + lane];
        acc.x += w0 * h0.x + w1 * h1.x;
        acc.y += w0 * h0.y + w1 * h1.y;
        acc.z += w0 * h0.z + w1 * h1.z;
        acc.w += w0 * h0.w + w1 * h1.w;
    }
    if (k < c) {
        int s0 = psrc[o + k];
        float w0 = wsrc[o + k];
        float4 h0 = v4[(size_t)s0 * 32 + lane];
        acc.x += w0 * h0.x; acc.y += w0 * h0.y; acc.z += w0 * h0.z; acc.w += w0 * h0.w;
    }
    const float di = dis[i];
    const float sn = di * di;
    size_t ib = (size_t)i * 32 + lane;
    float4 vs = v4[ib];
    float4 B = reinterpret_cast<const float4*>(bhh)[lane];
    float4 pv = reinterpret_cast<const float4*>(ph)[ib];
    float4 zv = reinterpret_cast<const float4*>(zg)[ib];
    float4 h0r = reinterpret_cast<const float4*>(hold)[lane];
    float4 r;
    float hhx = tanhf(pv.x + acc.x + vs.x * sn + B.x);
    float hhy = tanhf(pv.y + acc.y + vs.y * sn + B.y);
    float hhz = tanhf(pv.z + acc.z + vs.z * sn + B.z);
    float hhw = tanhf(pv.w + acc.w + vs.w * sn + B.w);
    r.x = zv.x * h0r.x + (1.0f - zv.x) * hhx;
    r.y = zv.y * h0r.y + (1.0f - zv.y) * hhy;
    r.z = zv.z * h0r.z + (1.0f - zv.z) * hhz;
    r.w = zv.w * h0r.w + (1.0f - zv.w) * hhw;
    reinterpret_cast<float4*>(hnew)[ib] = r;
}

// ---------------- host-side GEMM wrappers ----------------
static constexpr int SMEM_FK(int F, int K) {
    return (64 * (K + 8) + F * (K + 8)) * 2 * 2;  // (A + W) x (hi+lo) bf16
}

extern "C" void kernel_launch(void* const* d_in, const int* in_sizes, int n_in,
                              void* d_out, int out_size) {
    (void)in_sizes; (void)n_in; (void)out_size;
    const float* x   = (const float*)d_in[0];
    const int*   ei  = (const int*)d_in[1];
    const float* Wpx = (const float*)d_in[2];  const float* bpx = (const float*)d_in[3];
    // d_in[4..9] dead (prior MLPs)
    const float* Wc1 = (const float*)d_in[10]; const float* bc1 = (const float*)d_in[11];
    const float* Wm  = (const float*)d_in[12]; const float* bm  = (const float*)d_in[13];
    const float* Wpz = (const float*)d_in[14]; const float* bpz = (const float*)d_in[15];
    const float* Wxz = (const float*)d_in[16]; const float* bxz = (const float*)d_in[17];
    const float* Whz = (const float*)d_in[18]; const float* bhz = (const float*)d_in[19];
    const float* Wxr = (const float*)d_in[20]; const float* bxr = (const float*)d_in[21];
    const float* Whr = (const float*)d_in[22]; const float* bhr = (const float*)d_in[23];
    const float* Wxh = (const float*)d_in[24]; const float* bxh = (const float*)d_in[25];
    const float* Whh = (const float*)d_in[26]; const float* bhh = (const float*)d_in[27];
    float* out = (float*)d_out;

    cudaFuncSetAttribute(tcgemm_k<128, 128>, cudaFuncAttributeMaxDynamicSharedMemorySize, SMEM_FK(128, 128));
    cudaFuncSetAttribute(tcgemm_k<64, 128>,  cudaFuncAttributeMaxDynamicSharedMemorySize, SMEM_FK(64, 128));
    cudaFuncSetAttribute(tcgemm_k<128, 64>,  cudaFuncAttributeMaxDynamicSharedMemorySize, SMEM_FK(128, 64));
    cudaFuncSetAttribute(tcgemm2_k,          cudaFuncAttributeMaxDynamicSharedMemorySize, SMEM_FK(128, 128));

    float* base = nullptr;
    cudaGetSymbolAddress((void**)&base, g_scratch);
    __nv_bfloat16* whi = nullptr;
    cudaGetSymbolAddress((void**)&whi, g_wbf);
    const int WTOT = 212992;
    __nv_bfloat16* wlo = whi + WTOT;

    const size_t NB = 6400000ull;   // N*128
    const size_t NZ = 3200000ull;   // N*64
    float* xp    = base + 0 * NB;
    float* hbuf0 = base + 1 * NB;
    float* hbuf1 = base + 2 * NB;
    float* hw1   = base + 3 * NB;
    float* e1    = base + 4 * NB;
    float* zp    = base + 5 * NB;
    float* uz    = base + 6 * NB;
    float* ur    = base + 7 * NB;
    float* uh    = base + 8 * NB;
    float* zgb   = base + 9 * NB;
    float* phb   = base + 10 * NB;
    float* rhb   = base + 11 * NB;
    float* vb    = base + 12 * NB;
    float* pc1   = base + 13 * NB;
    float* pxz   = base + 14 * NB;
    float* pxr   = base + 15 * NB;
    float* pxh   = base + 16 * NB;
    float* hw2   = base + 17 * NB;           // N*64
    float* dis   = hw2 + NZ;
    int*   cnt    = (int*)(dis + N_NODES);
    int*   off    = cnt + N_NODES;
    int*   cursor = off + N_NODES;
    int*   bsum   = cursor + N_NODES;
    int*   psrc   = bsum + 64;
    float* wsrc   = (float*)(psrc + N_EDGES);

    // weight table: 0..11 are [128,128], 12 = Wm [128,64], 13 = Wpz [64,128]
    WCvtTab tab;
    const int S = 128 * 128;
    tab.m[0]  = {Wpx,     128, 128, 0 * S};
    tab.m[1]  = {Wc1,     128, 128, 1 * S};   // top half
    tab.m[2]  = {Wc1 + S, 128, 128, 2 * S};   // bottom half
    tab.m[3]  = {Wxz,     128, 128, 3 * S};
    tab.m[4]  = {Wxz + S, 128, 128, 4 * S};
    tab.m[5]  = {Whz,     128, 128, 5 * S};
    tab.m[6]  = {Wxr,     128, 128, 6 * S};
    tab.m[7]  = {Wxr + S, 128, 128, 7 * S};
    tab.m[8]  = {Whr,     128, 128, 8 * S};
    tab.m[9]  = {Wxh,     128, 128, 9 * S};
    tab.m[10] = {Wxh + S, 128, 128, 10 * S};
    tab.m[11] = {Whh,     128, 128, 11 * S};
    tab.m[12] = {Wm,      128, 64,  12 * S};
    tab.m[13] = {Wpz,     64,  128, 12 * S + 8192};

    const int N = N_NODES, E = N_EDGES;
    dim3 b256(256);
    const int gE = (E + 255) / 256;
    const int gN = (N + 255) / 256;
    const int gW = (N * 32 + 255) / 256;
    const int nScanBlocks = (N + 1023) / 1024;
    const int gG = (N + 63) / 64;   // GEMM grid (BM=64)

    float* hb[2] = {hbuf0, hbuf1};

    cudaMemsetAsync(hb[0], 0, NB * sizeof(float));

    // preconvert all weights once
    convw_k<<<dim3(64, 14), b256>>>(tab, whi, wlo);

    auto WH = [&](int m) { return whi + tab.m[m].off; };
    auto WL = [&](int m) { return wlo + tab.m[m].off; };

#define G128(Ap, m, Cp, Cadd, bias, act) \
    tcgemm_k<128, 128><<<gG, 256, SMEM_FK(128, 128)>>>(Ap, WH(m), WL(m), Cp, N, Cadd, bias, act)

    // time-invariant precomputes
    G128(x, 0, xp, nullptr, bpx, 1);
    G128(xp, 1, pc1, nullptr, nullptr, 0);
    G128(xp, 3, pxz, nullptr, nullptr, 0);
    G128(xp, 6, pxr, nullptr, nullptr, 0);
    G128(xp, 9, pxh, nullptr, nullptr, 0);

    for (int t = 0; t < T_STEPS; t++) {
        const int* src = ei + (size_t)t * 2 * E;
        const int* dst = src + E;
        float* hold = hb[t & 1];
        float* hnew = (t == T_STEPS - 1) ? (out + (size_t)T_STEPS * NZ) : hb[(t + 1) & 1];
        float* zt = out + (size_t)t * NZ;

        // ---- build CSR (by dst) + normalization coeffs (kept per-t for L2 locality) ----
        cudaMemsetAsync(cnt, 0, N * sizeof(int));
        count_k<<<gE, b256>>>(dst, cnt, E);
        scan1_k<<<nScanBlocks, 1024>>>(cnt, off, bsum, dis, N);
        scan2_k<<<1, 64>>>(bsum, nScanBlocks);
        scan3_k<<<gN, b256>>>(off, bsum, cursor, N);
        fill_k<<<gE, b256>>>(src, dst, dis, cursor, psrc, wsrc, E);

        // ---- e1 = relu(gcn(concat(xp,h) @ Wc1)) ----
        G128(hold, 2, hw1, pc1, nullptr, 0);
        gather_e1_k<<<gW, b256>>>(hw1, off, cnt, psrc, wsrc, dis, bc1, e1, N);

        // ---- z = gcn(e1 @ Wm) -> out slot t ----
        tcgemm_k<64, 128><<<gG, 256, SMEM_FK(64, 128)>>>(e1, WH(12), WL(12), hw2, N,
                                                         nullptr, nullptr, 0);
        gather_z_k<<<gW, b256>>>(hw2, off, cnt, psrc, wsrc, dis, bm, zt, N);

        // ---- zp = relu(z @ Wpz + bpz) ----
        tcgemm_k<128, 64><<<gG, 256, SMEM_FK(128, 64)>>>(zt, WH(13), WL(13), zp, N,
                                                         nullptr, bpz, 1);

        // ---- fused GRU linears ----
        tcgemm2_k<<<gG, 256, SMEM_FK(128, 128)>>>(zp, WH(4), WL(4), hold, WH(5), WL(5),
                                                  uz, N, pxz);
        tcgemm2_k<<<gG, 256, SMEM_FK(128, 128)>>>(zp, WH(7), WL(7), hold, WH(8), WL(8),
                                                  ur, N, pxr);
        G128(zp, 10, uh, pxh, nullptr, 0);

        // ---- triple gather + gates ----
        gather_gates_k<<<gW, b256>>>(uz, ur, uh, off, cnt, psrc, wsrc, dis,
                                     bxz, bhz, bxr, bhr, bxh, hold,
                                     zgb, phb, rhb, N);

        // ---- v = (rg*h) @ Whh ; gather + h update ----
        G128(rhb, 11, vb, nullptr, nullptr, 0);
        gather_hup_k<<<gW, b256>>>(vb, off, cnt, psrc, wsrc, dis, bhh, phb, zgb, hold, hnew, N);
    }
#undef G128
}